// round 2
// baseline (speedup 1.0000x reference)
#include <cuda_runtime.h>
#include <math.h>

// Problem constants (B=1)
#define T 2048   // tokens
#define H 1024   // hidden
#define II 4096  // intermediate
#define E 8      // experts
// Tiling
#define BM 64
#define BN 64
#define BK 16

// ---------------- scratch (device globals: allocation-free rule) ----------------
__device__ int   g_cnt[E];
__device__ int   g_off[E];          // exclusive prefix of g_cnt
__device__ int   g_tok[E][T];
__device__ float g_wt[E][T];
// compact hidden pool: exactly 2T expert-rows total (top-2 routing)
__device__ float g_hid[(size_t)2 * T * II];   // 64 MB

// ---------------- kernel 0: zero output + counters ----------------
__global__ void zero_kernel(float* __restrict__ out) {
    int i = blockIdx.x * blockDim.x + threadIdx.x;
    if (i < T * H) out[i] = 0.f;
    if (i < E) g_cnt[i] = 0;
}

// ---------------- kernel 1: gate logits -> top2 -> grouped lists ----------------
// one block per token, 8 warps, warp w computes logit for expert w
__global__ __launch_bounds__(256) void gate_kernel(const float* __restrict__ x,
                                                   const float* __restrict__ gw) {
    int t = blockIdx.x;
    int warp = threadIdx.x >> 5;
    int lane = threadIdx.x & 31;

    const float4* xr = (const float4*)(x + (size_t)t * H);
    const float4* gr = (const float4*)(gw + (size_t)warp * H);
    float s = 0.f;
    for (int j = lane; j < H / 4; j += 32) {
        float4 a = xr[j], b = gr[j];
        s += a.x * b.x + a.y * b.y + a.z * b.z + a.w * b.w;
    }
    #pragma unroll
    for (int o = 16; o > 0; o >>= 1) s += __shfl_xor_sync(0xffffffffu, s, o);

    __shared__ float lg[E];
    if (lane == 0) lg[warp] = s;
    __syncthreads();

    if (threadIdx.x == 0) {
        // top-2 by logit (softmax is monotone in logit)
        int e0 = 0;
        #pragma unroll
        for (int e = 1; e < E; e++) if (lg[e] > lg[e0]) e0 = e;
        int e1 = -1;
        #pragma unroll
        for (int e = 0; e < E; e++) {
            if (e == e0) continue;
            if (e1 < 0 || lg[e] > lg[e1]) e1 = e;
        }
        // renormalized top-2 softmax weights: w0 = 1/(1+exp(l1-l0))
        float d = expf(lg[e1] - lg[e0]);
        float w0 = 1.f / (1.f + d);
        float w1v = d / (1.f + d);
        int p0 = atomicAdd(&g_cnt[e0], 1);
        g_tok[e0][p0] = t; g_wt[e0][p0] = w0;
        int p1 = atomicAdd(&g_cnt[e1], 1);
        g_tok[e1][p1] = t; g_wt[e1][p1] = w1v;
    }
}

// ---------------- kernel 1b: exclusive prefix of counts ----------------
__global__ void prefix_kernel() {
    if (threadIdx.x == 0 && blockIdx.x == 0) {
        int acc = 0;
        #pragma unroll
        for (int e = 0; e < E; e++) { g_off[e] = acc; acc += g_cnt[e]; }
    }
}

// ---------------- kernel 2: per-expert GEMM1 + silu ----------------
// hid[off[e]+m][i] = silu( sum_h x[tok[e][m]][h] * w1[e][i][h] )
__global__ __launch_bounds__(256) void gemm1_kernel(const float* __restrict__ x,
                                                    const float* __restrict__ w1) {
    int e = blockIdx.z;
    int cnt = g_cnt[e];
    int m0 = blockIdx.y * BM;
    if (m0 >= cnt) return;
    int n0 = blockIdx.x * BN;
    int base = g_off[e];

    __shared__ float As[BM][BK + 1];
    __shared__ float Bs[BN][BK + 1];
    __shared__ int   stok[BM];

    int tid = threadIdx.x;
    int tx = tid & 15, ty = tid >> 4;

    if (tid < BM) {
        int m = m0 + tid;
        stok[tid] = (m < cnt) ? g_tok[e][m] : g_tok[e][cnt - 1];
    }
    __syncthreads();

    const float* w1e = w1 + (size_t)e * II * H;
    int lr = tid >> 2;          // 0..63
    int lc = (tid & 3) * 4;     // 0,4,8,12

    float acc[4][4] = {};
    int arow = stok[lr];

    for (int k0 = 0; k0 < H; k0 += BK) {
        float4 av = *(const float4*)(x + (size_t)arow * H + k0 + lc);
        float4 bv = *(const float4*)(w1e + (size_t)(n0 + lr) * H + k0 + lc);
        As[lr][lc + 0] = av.x; As[lr][lc + 1] = av.y; As[lr][lc + 2] = av.z; As[lr][lc + 3] = av.w;
        Bs[lr][lc + 0] = bv.x; Bs[lr][lc + 1] = bv.y; Bs[lr][lc + 2] = bv.z; Bs[lr][lc + 3] = bv.w;
        __syncthreads();
        #pragma unroll
        for (int k = 0; k < BK; k++) {
            float a[4], b[4];
            #pragma unroll
            for (int j = 0; j < 4; j++) a[j] = As[ty * 4 + j][k];
            #pragma unroll
            for (int j = 0; j < 4; j++) b[j] = Bs[tx * 4 + j][k];
            #pragma unroll
            for (int jm = 0; jm < 4; jm++)
                #pragma unroll
                for (int jn = 0; jn < 4; jn++)
                    acc[jm][jn] += a[jm] * b[jn];
        }
        __syncthreads();
    }

    #pragma unroll
    for (int jm = 0; jm < 4; jm++) {
        int m = m0 + ty * 4 + jm;
        if (m >= cnt) break;
        float* hrow = g_hid + ((size_t)(base + m)) * II;
        #pragma unroll
        for (int jn = 0; jn < 4; jn++) {
            int n = n0 + tx * 4 + jn;
            float v = acc[jm][jn];
            hrow[n] = v / (1.f + expf(-v));   // silu
        }
    }
}

// ---------------- kernel 3: per-expert GEMM2 + weighted scatter-add ----------------
// out[tok[e][m]][h] += wt[e][m] * sum_i hid[off[e]+m][i] * w2[e][h][i]
__global__ __launch_bounds__(256) void gemm2_kernel(const float* __restrict__ w2,
                                                    float* __restrict__ out) {
    int e = blockIdx.z;
    int cnt = g_cnt[e];
    int m0 = blockIdx.y * BM;
    if (m0 >= cnt) return;
    int n0 = blockIdx.x * BN;
    int base = g_off[e];

    __shared__ float As[BM][BK + 1];
    __shared__ float Bs[BN][BK + 1];

    int tid = threadIdx.x;
    int tx = tid & 15, ty = tid >> 4;
    int lr = tid >> 2;
    int lc = (tid & 3) * 4;

    const float* w2e = w2 + (size_t)e * H * II;

    float acc[4][4] = {};
    // clamp A row so we never read outside this expert's pool segment
    int am = m0 + lr; if (am >= cnt) am = cnt - 1;
    const float* arow = g_hid + (size_t)(base + am) * II;

    for (int k0 = 0; k0 < II; k0 += BK) {
        float4 av = *(const float4*)(arow + k0 + lc);
        float4 bv = *(const float4*)(w2e + (size_t)(n0 + lr) * II + k0 + lc);
        As[lr][lc + 0] = av.x; As[lr][lc + 1] = av.y; As[lr][lc + 2] = av.z; As[lr][lc + 3] = av.w;
        Bs[lr][lc + 0] = bv.x; Bs[lr][lc + 1] = bv.y; Bs[lr][lc + 2] = bv.z; Bs[lr][lc + 3] = bv.w;
        __syncthreads();
        #pragma unroll
        for (int k = 0; k < BK; k++) {
            float a[4], b[4];
            #pragma unroll
            for (int j = 0; j < 4; j++) a[j] = As[ty * 4 + j][k];
            #pragma unroll
            for (int j = 0; j < 4; j++) b[j] = Bs[tx * 4 + j][k];
            #pragma unroll
            for (int jm = 0; jm < 4; jm++)
                #pragma unroll
                for (int jn = 0; jn < 4; jn++)
                    acc[jm][jn] += a[jm] * b[jn];
        }
        __syncthreads();
    }

    #pragma unroll
    for (int jm = 0; jm < 4; jm++) {
        int m = m0 + ty * 4 + jm;
        if (m >= cnt) break;
        int tok = g_tok[e][m];
        float wt = g_wt[e][m];
        float* orow = out + (size_t)tok * H;
        #pragma unroll
        for (int jn = 0; jn < 4; jn++) {
            int n = n0 + tx * 4 + jn;
            atomicAdd(orow + n, wt * acc[jm][jn]);
        }
    }
}

// ---------------- launch ----------------
extern "C" void kernel_launch(void* const* d_in, const int* in_sizes, int n_in,
                              void* d_out, int out_size) {
    const float* x  = (const float*)d_in[0];   // [1,2048,1024]
    const float* gw = (const float*)d_in[1];   // [8,1024]
    const float* w1 = (const float*)d_in[2];   // [8,4096,1024]
    const float* w2 = (const float*)d_in[3];   // [8,1024,4096]
    float* out = (float*)d_out;                // [1,2048,1024]

    zero_kernel<<<(T * H + 255) / 256, 256>>>(out);
    gate_kernel<<<T, 256>>>(x, gw);
    prefix_kernel<<<1, 32>>>();
    gemm1_kernel<<<dim3(II / BN, T / BM, E), 256>>>(x, w1);
    gemm2_kernel<<<dim3(H / BN, T / BM, E), 256>>>(w2, out);
}

// round 4
// speedup vs baseline: 2.2098x; 2.2098x over previous
#include <cuda_runtime.h>
#include <cuda_bf16.h>
#include <math.h>
#include <stdint.h>

// Problem constants (B=1)
#define T 2048
#define H 1024
#define II 4096
#define E 8

// Tiling
#define BM 128
#define BN 128
#define KC 32            // K elems per chunk
#define RS 40            // smem row stride in bf16 elems (32 + pad 8 -> 80B, 16B aligned)

#define TILE_B (BM * RS * 2)          // 10240 bytes per tile
#define SM_TOK   0
#define SM_TILES 1024
#define OFF_AH(b) (SM_TILES + (b) * (4 * TILE_B) + 0 * TILE_B)
#define OFF_AL(b) (SM_TILES + (b) * (4 * TILE_B) + 1 * TILE_B)
#define OFF_BH(b) (SM_TILES + (b) * (4 * TILE_B) + 2 * TILE_B)
#define OFF_BL(b) (SM_TILES + (b) * (4 * TILE_B) + 3 * TILE_B)
#define SMEM_TOTAL (SM_TILES + 8 * TILE_B)   // 82944 bytes

// ---------------- scratch ----------------
__device__ int   g_cnt[E];
__device__ int   g_off[E];
__device__ int   g_tok[E][T];
__device__ float g_wt[E][T];
__device__ __nv_bfloat16 g_hid_hi[(size_t)2 * T * II];
__device__ __nv_bfloat16 g_hid_lo[(size_t)2 * T * II];

// ---------------- helpers ----------------
__device__ __forceinline__ uint32_t smem_u32(const void* p) {
    uint32_t a;
    asm("{ .reg .u64 t; cvta.to.shared.u64 t, %1; cvt.u32.u64 %0, t; }" : "=r"(a) : "l"(p));
    return a;
}
__device__ __forceinline__ void ldsm4(uint32_t* r, uint32_t addr) {
    asm volatile("ldmatrix.sync.aligned.m8n8.x4.shared.b16 {%0,%1,%2,%3}, [%4];"
                 : "=r"(r[0]), "=r"(r[1]), "=r"(r[2]), "=r"(r[3]) : "r"(addr));
}
__device__ __forceinline__ void mma16816(float* d, const uint32_t* a, const uint32_t* b) {
    asm volatile("mma.sync.aligned.m16n8k16.row.col.f32.bf16.bf16.f32 "
                 "{%0,%1,%2,%3}, {%4,%5,%6,%7}, {%8,%9}, {%0,%1,%2,%3};"
                 : "+f"(d[0]), "+f"(d[1]), "+f"(d[2]), "+f"(d[3])
                 : "r"(a[0]), "r"(a[1]), "r"(a[2]), "r"(a[3]), "r"(b[0]), "r"(b[1]));
}
// split fp32x4 -> 4 bf16 hi (uint2) + 4 bf16 lo (uint2)
__device__ __forceinline__ void split4(float4 v, uint2& hi, uint2& lo) {
    float f0 = v.x, f1 = v.y, f2 = v.z, f3 = v.w;
    unsigned h0 = __bfloat16_as_ushort(__float2bfloat16(f0));
    unsigned h1 = __bfloat16_as_ushort(__float2bfloat16(f1));
    unsigned h2 = __bfloat16_as_ushort(__float2bfloat16(f2));
    unsigned h3 = __bfloat16_as_ushort(__float2bfloat16(f3));
    float r0 = f0 - __bfloat162float(__ushort_as_bfloat16((unsigned short)h0));
    float r1 = f1 - __bfloat162float(__ushort_as_bfloat16((unsigned short)h1));
    float r2 = f2 - __bfloat162float(__ushort_as_bfloat16((unsigned short)h2));
    float r3 = f3 - __bfloat162float(__ushort_as_bfloat16((unsigned short)h3));
    unsigned l0 = __bfloat16_as_ushort(__float2bfloat16(r0));
    unsigned l1 = __bfloat16_as_ushort(__float2bfloat16(r1));
    unsigned l2 = __bfloat16_as_ushort(__float2bfloat16(r2));
    unsigned l3 = __bfloat16_as_ushort(__float2bfloat16(r3));
    hi.x = h0 | (h1 << 16); hi.y = h2 | (h3 << 16);
    lo.x = l0 | (l1 << 16); lo.y = l2 | (l3 << 16);
}
// pack two fp32 as two bf16 into u32 (hi) and residual (lo)
__device__ __forceinline__ void split2(float a, float b, uint32_t& hi, uint32_t& lo) {
    unsigned ha = __bfloat16_as_ushort(__float2bfloat16(a));
    unsigned hb = __bfloat16_as_ushort(__float2bfloat16(b));
    float ra = a - __bfloat162float(__ushort_as_bfloat16((unsigned short)ha));
    float rb = b - __bfloat162float(__ushort_as_bfloat16((unsigned short)hb));
    unsigned la = __bfloat16_as_ushort(__float2bfloat16(ra));
    unsigned lb = __bfloat16_as_ushort(__float2bfloat16(rb));
    hi = ha | (hb << 16);
    lo = la | (lb << 16);
}

// ---------------- kernel 0: zero output + counters ----------------
__global__ void zero_kernel(float* __restrict__ out) {
    int i = blockIdx.x * blockDim.x + threadIdx.x;
    if (i < T * H) out[i] = 0.f;
    if (i < E) g_cnt[i] = 0;
}

// ---------------- kernel 1: gate -> top2 -> grouped lists ----------------
__global__ __launch_bounds__(256) void gate_kernel(const float* __restrict__ x,
                                                   const float* __restrict__ gw) {
    int t = blockIdx.x;
    int warp = threadIdx.x >> 5;
    int lane = threadIdx.x & 31;

    const float4* xr = (const float4*)(x + (size_t)t * H);
    const float4* gr = (const float4*)(gw + (size_t)warp * H);
    float s = 0.f;
    for (int j = lane; j < H / 4; j += 32) {
        float4 a = xr[j], b = gr[j];
        s += a.x * b.x + a.y * b.y + a.z * b.z + a.w * b.w;
    }
    #pragma unroll
    for (int o = 16; o > 0; o >>= 1) s += __shfl_xor_sync(0xffffffffu, s, o);

    __shared__ float lg[E];
    if (lane == 0) lg[warp] = s;
    __syncthreads();

    if (threadIdx.x == 0) {
        int e0 = 0;
        #pragma unroll
        for (int e = 1; e < E; e++) if (lg[e] > lg[e0]) e0 = e;
        int e1 = -1;
        #pragma unroll
        for (int e = 0; e < E; e++) {
            if (e == e0) continue;
            if (e1 < 0 || lg[e] > lg[e1]) e1 = e;
        }
        float d = expf(lg[e1] - lg[e0]);
        float w0 = 1.f / (1.f + d);
        float w1v = d / (1.f + d);
        int p0 = atomicAdd(&g_cnt[e0], 1);
        g_tok[e0][p0] = t; g_wt[e0][p0] = w0;
        int p1 = atomicAdd(&g_cnt[e1], 1);
        g_tok[e1][p1] = t; g_wt[e1][p1] = w1v;
    }
}

__global__ void prefix_kernel() {
    if (threadIdx.x == 0 && blockIdx.x == 0) {
        int acc = 0;
        #pragma unroll
        for (int e = 0; e < E; e++) { g_off[e] = acc; acc += g_cnt[e]; }
    }
}

// ---------------- kernel 2: grouped GEMM1 (mma.sync bf16-split) + silu ----------------
__global__ __launch_bounds__(256, 1) void gemm1_tc(const float* __restrict__ x,
                                                   const float* __restrict__ w1) {
    extern __shared__ char smem[];
    int e = blockIdx.z;
    int cnt = g_cnt[e];
    int m0 = blockIdx.y * BM;
    if (m0 >= cnt) return;
    int n0 = blockIdx.x * BN;
    int base = g_off[e];
    int tid = threadIdx.x, wid = tid >> 5, lane = tid & 31;

    int* stok = (int*)(smem + SM_TOK);
    if (tid < BM) {
        int m = m0 + tid;
        stok[tid] = g_tok[e][m < cnt ? m : cnt - 1];
    }
    __syncthreads();
    uint32_t sb = smem_u32(smem);

    // gmem staging: thread covers row=tid/2, half=tid&1 -> 16 floats
    int row = tid >> 1, half = tid & 1;
    const float* ap = x + (size_t)stok[row] * H + half * 16;
    const float* bp = w1 + (size_t)e * II * H + (size_t)(n0 + row) * H + half * 16;
    uint32_t soff = (uint32_t)row * (RS * 2) + half * 32;   // byte off in tile

    int warp_m = wid >> 2, warp_n = wid & 3;
    int lr = lane & 15, lc8 = (lane >> 4) * 8;

    float acc[4][4][4];
    #pragma unroll
    for (int i = 0; i < 4; i++)
        #pragma unroll
        for (int j = 0; j < 4; j++)
            #pragma unroll
            for (int q = 0; q < 4; q++) acc[i][j][q] = 0.f;

    float4 ra[4], rb[4];
    const int NK = H / KC;   // 32

    // load + store chunk 0
    #pragma unroll
    for (int j = 0; j < 4; j++) { ra[j] = *(const float4*)(ap + j * 4); rb[j] = *(const float4*)(bp + j * 4); }
    #pragma unroll
    for (int j = 0; j < 4; j++) {
        uint2 hi, lo;
        split4(ra[j], hi, lo);
        *(uint2*)(smem + OFF_AH(0) + soff + j * 8) = hi;
        *(uint2*)(smem + OFF_AL(0) + soff + j * 8) = lo;
        split4(rb[j], hi, lo);
        *(uint2*)(smem + OFF_BH(0) + soff + j * 8) = hi;
        *(uint2*)(smem + OFF_BL(0) + soff + j * 8) = lo;
    }
    __syncthreads();

    for (int kc = 0; kc < NK; kc++) {
        int buf = kc & 1;
        if (kc + 1 < NK) {
            const float* a2 = ap + (kc + 1) * KC;
            const float* b2 = bp + (kc + 1) * KC;
            #pragma unroll
            for (int j = 0; j < 4; j++) { ra[j] = *(const float4*)(a2 + j * 4); rb[j] = *(const float4*)(b2 + j * 4); }
        }
        uint32_t ah_b = sb + OFF_AH(buf), al_b = sb + OFF_AL(buf);
        uint32_t bh_b = sb + OFF_BH(buf), bl_b = sb + OFF_BL(buf);
        #pragma unroll
        for (int kk = 0; kk < 2; kk++) {
            uint32_t colb = (kk * 16 + lc8) * 2;
            uint32_t Ah[4][4], Al[4][4], Bh[4][2], Bl[4][2];
            #pragma unroll
            for (int im = 0; im < 4; im++) {
                uint32_t aoff = (uint32_t)(warp_m * 64 + im * 16 + lr) * (RS * 2) + colb;
                ldsm4(Ah[im], ah_b + aoff);
                ldsm4(Al[im], al_b + aoff);
            }
            #pragma unroll
            for (int in2 = 0; in2 < 2; in2++) {
                uint32_t boff = (uint32_t)(warp_n * 32 + in2 * 16 + lr) * (RS * 2) + colb;
                uint32_t t[4];
                ldsm4(t, bh_b + boff);
                Bh[2 * in2][0] = t[0]; Bh[2 * in2][1] = t[2];
                Bh[2 * in2 + 1][0] = t[1]; Bh[2 * in2 + 1][1] = t[3];
                ldsm4(t, bl_b + boff);
                Bl[2 * in2][0] = t[0]; Bl[2 * in2][1] = t[2];
                Bl[2 * in2 + 1][0] = t[1]; Bl[2 * in2 + 1][1] = t[3];
            }
            #pragma unroll
            for (int im = 0; im < 4; im++)
                #pragma unroll
                for (int in = 0; in < 4; in++) {
                    mma16816(acc[im][in], Ah[im], Bh[in]);
                    mma16816(acc[im][in], Ah[im], Bl[in]);
                    mma16816(acc[im][in], Al[im], Bh[in]);
                }
        }
        __syncthreads();
        if (kc + 1 < NK) {
            int nb = buf ^ 1;
            #pragma unroll
            for (int j = 0; j < 4; j++) {
                uint2 hi, lo;
                split4(ra[j], hi, lo);
                *(uint2*)(smem + OFF_AH(nb) + soff + j * 8) = hi;
                *(uint2*)(smem + OFF_AL(nb) + soff + j * 8) = lo;
                split4(rb[j], hi, lo);
                *(uint2*)(smem + OFF_BH(nb) + soff + j * 8) = hi;
                *(uint2*)(smem + OFF_BL(nb) + soff + j * 8) = lo;
            }
            __syncthreads();
        }
    }

    // epilogue: silu + split -> g_hid hi/lo
    int quad = lane >> 2, tq = lane & 3;
    #pragma unroll
    for (int im = 0; im < 4; im++) {
        int mA = m0 + warp_m * 64 + im * 16 + quad;
        int mB = mA + 8;
        bool aA = (mA < cnt), aB = (mB < cnt);
        size_t roA = aA ? (size_t)(base + mA) * II : 0;
        size_t roB = aB ? (size_t)(base + mB) * II : 0;
        #pragma unroll
        for (int in = 0; in < 4; in++) {
            int col = n0 + warp_n * 32 + in * 8 + tq * 2;
            if (aA) {
                float v0 = acc[im][in][0], v1 = acc[im][in][1];
                v0 = v0 / (1.f + __expf(-v0));
                v1 = v1 / (1.f + __expf(-v1));
                uint32_t hi, lo;
                split2(v0, v1, hi, lo);
                *(uint32_t*)(g_hid_hi + roA + col) = hi;
                *(uint32_t*)(g_hid_lo + roA + col) = lo;
            }
            if (aB) {
                float v0 = acc[im][in][2], v1 = acc[im][in][3];
                v0 = v0 / (1.f + __expf(-v0));
                v1 = v1 / (1.f + __expf(-v1));
                uint32_t hi, lo;
                split2(v0, v1, hi, lo);
                *(uint32_t*)(g_hid_hi + roB + col) = hi;
                *(uint32_t*)(g_hid_lo + roB + col) = lo;
            }
        }
    }
}

// ---------------- kernel 3: grouped GEMM2 (mma.sync bf16-split) + scatter-add ----------------
__global__ __launch_bounds__(256, 1) void gemm2_tc(const float* __restrict__ w2,
                                                   float* __restrict__ out) {
    extern __shared__ char smem[];
    int e = blockIdx.z;
    int cnt = g_cnt[e];
    int m0 = blockIdx.y * BM;
    if (m0 >= cnt) return;
    int n0 = blockIdx.x * BN;
    int base = g_off[e];
    int tid = threadIdx.x, wid = tid >> 5, lane = tid & 31;
    uint32_t sb = smem_u32(smem);

    int row = tid >> 1, half = tid & 1;
    int am = m0 + row; if (am >= cnt) am = cnt - 1;
    const __nv_bfloat16* ahp = g_hid_hi + (size_t)(base + am) * II + half * 16;
    const __nv_bfloat16* alp = g_hid_lo + (size_t)(base + am) * II + half * 16;
    const float* bp = w2 + (size_t)e * H * II + (size_t)(n0 + row) * II + half * 16;
    uint32_t soff = (uint32_t)row * (RS * 2) + half * 32;

    int warp_m = wid >> 2, warp_n = wid & 3;
    int lr = lane & 15, lc8 = (lane >> 4) * 8;

    float acc[4][4][4];
    #pragma unroll
    for (int i = 0; i < 4; i++)
        #pragma unroll
        for (int j = 0; j < 4; j++)
            #pragma unroll
            for (int q = 0; q < 4; q++) acc[i][j][q] = 0.f;

    uint4 rah[2], ral[2];
    float4 rb[4];
    const int NK = II / KC;  // 128

    #pragma unroll
    for (int j = 0; j < 2; j++) { rah[j] = *(const uint4*)(ahp + j * 8); ral[j] = *(const uint4*)(alp + j * 8); }
    #pragma unroll
    for (int j = 0; j < 4; j++) rb[j] = *(const float4*)(bp + j * 4);
    #pragma unroll
    for (int j = 0; j < 2; j++) {
        *(uint4*)(smem + OFF_AH(0) + soff + j * 16) = rah[j];
        *(uint4*)(smem + OFF_AL(0) + soff + j * 16) = ral[j];
    }
    #pragma unroll
    for (int j = 0; j < 4; j++) {
        uint2 hi, lo;
        split4(rb[j], hi, lo);
        *(uint2*)(smem + OFF_BH(0) + soff + j * 8) = hi;
        *(uint2*)(smem + OFF_BL(0) + soff + j * 8) = lo;
    }
    __syncthreads();

    for (int kc = 0; kc < NK; kc++) {
        int buf = kc & 1;
        if (kc + 1 < NK) {
            const __nv_bfloat16* a2h = ahp + (kc + 1) * KC;
            const __nv_bfloat16* a2l = alp + (kc + 1) * KC;
            const float* b2 = bp + (kc + 1) * KC;
            #pragma unroll
            for (int j = 0; j < 2; j++) { rah[j] = *(const uint4*)(a2h + j * 8); ral[j] = *(const uint4*)(a2l + j * 8); }
            #pragma unroll
            for (int j = 0; j < 4; j++) rb[j] = *(const float4*)(b2 + j * 4);
        }
        uint32_t ah_b = sb + OFF_AH(buf), al_b = sb + OFF_AL(buf);
        uint32_t bh_b = sb + OFF_BH(buf), bl_b = sb + OFF_BL(buf);
        #pragma unroll
        for (int kk = 0; kk < 2; kk++) {
            uint32_t colb = (kk * 16 + lc8) * 2;
            uint32_t Ah[4][4], Al[4][4], Bh[4][2], Bl[4][2];
            #pragma unroll
            for (int im = 0; im < 4; im++) {
                uint32_t aoff = (uint32_t)(warp_m * 64 + im * 16 + lr) * (RS * 2) + colb;
                ldsm4(Ah[im], ah_b + aoff);
                ldsm4(Al[im], al_b + aoff);
            }
            #pragma unroll
            for (int in2 = 0; in2 < 2; in2++) {
                uint32_t boff = (uint32_t)(warp_n * 32 + in2 * 16 + lr) * (RS * 2) + colb;
                uint32_t t[4];
                ldsm4(t, bh_b + boff);
                Bh[2 * in2][0] = t[0]; Bh[2 * in2][1] = t[2];
                Bh[2 * in2 + 1][0] = t[1]; Bh[2 * in2 + 1][1] = t[3];
                ldsm4(t, bl_b + boff);
                Bl[2 * in2][0] = t[0]; Bl[2 * in2][1] = t[2];
                Bl[2 * in2 + 1][0] = t[1]; Bl[2 * in2 + 1][1] = t[3];
            }
            #pragma unroll
            for (int im = 0; im < 4; im++)
                #pragma unroll
                for (int in = 0; in < 4; in++) {
                    mma16816(acc[im][in], Ah[im], Bh[in]);
                    mma16816(acc[im][in], Ah[im], Bl[in]);
                    mma16816(acc[im][in], Al[im], Bh[in]);
                }
        }
        __syncthreads();
        if (kc + 1 < NK) {
            int nb = buf ^ 1;
            #pragma unroll
            for (int j = 0; j < 2; j++) {
                *(uint4*)(smem + OFF_AH(nb) + soff + j * 16) = rah[j];
                *(uint4*)(smem + OFF_AL(nb) + soff + j * 16) = ral[j];
            }
            #pragma unroll
            for (int j = 0; j < 4; j++) {
                uint2 hi, lo;
                split4(rb[j], hi, lo);
                *(uint2*)(smem + OFF_BH(nb) + soff + j * 8) = hi;
                *(uint2*)(smem + OFF_BL(nb) + soff + j * 8) = lo;
            }
            __syncthreads();
        }
    }

    // epilogue: weighted scatter-add
    int quad = lane >> 2, tq = lane & 3;
    #pragma unroll
    for (int im = 0; im < 4; im++) {
        int mA = m0 + warp_m * 64 + im * 16 + quad;
        int mB = mA + 8;
        bool aA = (mA < cnt), aB = (mB < cnt);
        int tokA = aA ? g_tok[e][mA] : 0;  float wtA = aA ? g_wt[e][mA] : 0.f;
        int tokB = aB ? g_tok[e][mB] : 0;  float wtB = aB ? g_wt[e][mB] : 0.f;
        float* oA = out + (size_t)tokA * H;
        float* oB = out + (size_t)tokB * H;
        #pragma unroll
        for (int in = 0; in < 4; in++) {
            int col = n0 + warp_n * 32 + in * 8 + tq * 2;
            if (aA) {
                atomicAdd(oA + col,     wtA * acc[im][in][0]);
                atomicAdd(oA + col + 1, wtA * acc[im][in][1]);
            }
            if (aB) {
                atomicAdd(oB + col,     wtB * acc[im][in][2]);
                atomicAdd(oB + col + 1, wtB * acc[im][in][3]);
            }
        }
    }
}

// ---------------- launch ----------------
extern "C" void kernel_launch(void* const* d_in, const int* in_sizes, int n_in,
                              void* d_out, int out_size) {
    const float* x  = (const float*)d_in[0];   // [1,2048,1024]
    const float* gw = (const float*)d_in[1];   // [8,1024]
    const float* w1 = (const float*)d_in[2];   // [8,4096,1024]
    const float* w2 = (const float*)d_in[3];   // [8,1024,4096]
    float* out = (float*)d_out;                // [1,2048,1024]

    cudaFuncSetAttribute(gemm1_tc, cudaFuncAttributeMaxDynamicSharedMemorySize, SMEM_TOTAL);
    cudaFuncSetAttribute(gemm2_tc, cudaFuncAttributeMaxDynamicSharedMemorySize, SMEM_TOTAL);

    zero_kernel<<<(T * H + 255) / 256, 256>>>(out);
    gate_kernel<<<T, 256>>>(x, gw);
    prefix_kernel<<<1, 32>>>();
    gemm1_tc<<<dim3(II / BN, T / BM, E), 256, SMEM_TOTAL>>>(x, w1);
    gemm2_tc<<<dim3(H / BN, T / BM, E), 256, SMEM_TOTAL>>>(w2, out);
}

// round 5
// speedup vs baseline: 2.2232x; 1.0061x over previous
#include <cuda_runtime.h>
#include <cuda_bf16.h>
#include <math.h>
#include <stdint.h>

// Problem constants (B=1)
#define T 2048
#define H 1024
#define II 4096
#define E 8

// Tiling
#define BM 128
#define BN 128
#define KC 32              // K elems (bf16) per chunk
#define RSB 80             // smem row stride bytes (64B data + 16B pad)
#define STAGES 3

#define TILE_B (BM * RSB)                      // 10240 B
#define STG_B  (4 * TILE_B)                    // Ah, Al, Bh, Bl = 40960 B
#define SM_TOK   0
#define SM_TILES 1024
#define OFF_T(s, t) (SM_TILES + (s) * STG_B + (t) * TILE_B)
#define SMEM_TOTAL (SM_TILES + STAGES * STG_B)   // 123904 B

// ---------------- scratch (device globals) ----------------
__device__ int   g_cnt[E];
__device__ int   g_off[E];
__device__ int   g_tok[E][T];
__device__ float g_wt[E][T];
__device__ __nv_bfloat16 g_xh[(size_t)T * H];
__device__ __nv_bfloat16 g_xl[(size_t)T * H];
__device__ __nv_bfloat16 g_w1h[(size_t)E * II * H];
__device__ __nv_bfloat16 g_w1l[(size_t)E * II * H];
__device__ __nv_bfloat16 g_w2h[(size_t)E * H * II];
__device__ __nv_bfloat16 g_w2l[(size_t)E * H * II];
__device__ __nv_bfloat16 g_hid_hi[(size_t)2 * T * II];
__device__ __nv_bfloat16 g_hid_lo[(size_t)2 * T * II];

// ---------------- helpers ----------------
__device__ __forceinline__ uint32_t smem_u32(const void* p) {
    uint32_t a;
    asm("{ .reg .u64 t; cvta.to.shared.u64 t, %1; cvt.u32.u64 %0, t; }" : "=r"(a) : "l"(p));
    return a;
}
__device__ __forceinline__ void cp16(uint32_t s, const void* g) {
    asm volatile("cp.async.cg.shared.global [%0], [%1], 16;" :: "r"(s), "l"(g));
}
__device__ __forceinline__ void cp_commit() {
    asm volatile("cp.async.commit_group;" ::: "memory");
}
template <int N>
__device__ __forceinline__ void cp_wait() {
    asm volatile("cp.async.wait_group %0;" :: "n"(N) : "memory");
}
__device__ __forceinline__ void ldsm4(uint32_t* r, uint32_t addr) {
    asm volatile("ldmatrix.sync.aligned.m8n8.x4.shared.b16 {%0,%1,%2,%3}, [%4];"
                 : "=r"(r[0]), "=r"(r[1]), "=r"(r[2]), "=r"(r[3]) : "r"(addr));
}
__device__ __forceinline__ void mma16816(float* d, const uint32_t* a, const uint32_t* b) {
    asm volatile("mma.sync.aligned.m16n8k16.row.col.f32.bf16.bf16.f32 "
                 "{%0,%1,%2,%3}, {%4,%5,%6,%7}, {%8,%9}, {%0,%1,%2,%3};"
                 : "+f"(d[0]), "+f"(d[1]), "+f"(d[2]), "+f"(d[3])
                 : "r"(a[0]), "r"(a[1]), "r"(a[2]), "r"(a[3]), "r"(b[0]), "r"(b[1]));
}
__device__ __forceinline__ void split4(float4 v, uint2& hi, uint2& lo) {
    float f0 = v.x, f1 = v.y, f2 = v.z, f3 = v.w;
    unsigned h0 = __bfloat16_as_ushort(__float2bfloat16(f0));
    unsigned h1 = __bfloat16_as_ushort(__float2bfloat16(f1));
    unsigned h2 = __bfloat16_as_ushort(__float2bfloat16(f2));
    unsigned h3 = __bfloat16_as_ushort(__float2bfloat16(f3));
    float r0 = f0 - __bfloat162float(__ushort_as_bfloat16((unsigned short)h0));
    float r1 = f1 - __bfloat162float(__ushort_as_bfloat16((unsigned short)h1));
    float r2 = f2 - __bfloat162float(__ushort_as_bfloat16((unsigned short)h2));
    float r3 = f3 - __bfloat162float(__ushort_as_bfloat16((unsigned short)h3));
    unsigned l0 = __bfloat16_as_ushort(__float2bfloat16(r0));
    unsigned l1 = __bfloat16_as_ushort(__float2bfloat16(r1));
    unsigned l2 = __bfloat16_as_ushort(__float2bfloat16(r2));
    unsigned l3 = __bfloat16_as_ushort(__float2bfloat16(r3));
    hi.x = h0 | (h1 << 16); hi.y = h2 | (h3 << 16);
    lo.x = l0 | (l1 << 16); lo.y = l2 | (l3 << 16);
}
__device__ __forceinline__ void split2(float a, float b, uint32_t& hi, uint32_t& lo) {
    unsigned ha = __bfloat16_as_ushort(__float2bfloat16(a));
    unsigned hb = __bfloat16_as_ushort(__float2bfloat16(b));
    float ra = a - __bfloat162float(__ushort_as_bfloat16((unsigned short)ha));
    float rb = b - __bfloat162float(__ushort_as_bfloat16((unsigned short)hb));
    unsigned la = __bfloat16_as_ushort(__float2bfloat16(ra));
    unsigned lb = __bfloat16_as_ushort(__float2bfloat16(rb));
    hi = ha | (hb << 16);
    lo = la | (lb << 16);
}

// ---------------- kernel: fp32 -> bf16 hi/lo split (grid-stride) ----------------
__global__ void split_kernel(const float* __restrict__ src,
                             __nv_bfloat16* __restrict__ hi,
                             __nv_bfloat16* __restrict__ lo, int n4) {
    int i = blockIdx.x * blockDim.x + threadIdx.x;
    if (i < n4) {
        float4 v = ((const float4*)src)[i];
        uint2 h, l;
        split4(v, h, l);
        ((uint2*)hi)[i] = h;
        ((uint2*)lo)[i] = l;
    }
}

// ---------------- kernel 0: zero output + counters ----------------
__global__ void zero_kernel(float* __restrict__ out) {
    int i = blockIdx.x * blockDim.x + threadIdx.x;
    if (i < T * H) out[i] = 0.f;
    if (i < E) g_cnt[i] = 0;
}

// ---------------- kernel 1: gate -> top2 -> grouped lists ----------------
__global__ __launch_bounds__(256) void gate_kernel(const float* __restrict__ x,
                                                   const float* __restrict__ gw) {
    int t = blockIdx.x;
    int warp = threadIdx.x >> 5;
    int lane = threadIdx.x & 31;

    const float4* xr = (const float4*)(x + (size_t)t * H);
    const float4* gr = (const float4*)(gw + (size_t)warp * H);
    float s = 0.f;
    for (int j = lane; j < H / 4; j += 32) {
        float4 a = xr[j], b = gr[j];
        s += a.x * b.x + a.y * b.y + a.z * b.z + a.w * b.w;
    }
    #pragma unroll
    for (int o = 16; o > 0; o >>= 1) s += __shfl_xor_sync(0xffffffffu, s, o);

    __shared__ float lg[E];
    if (lane == 0) lg[warp] = s;
    __syncthreads();

    if (threadIdx.x == 0) {
        int e0 = 0;
        #pragma unroll
        for (int e = 1; e < E; e++) if (lg[e] > lg[e0]) e0 = e;
        int e1 = -1;
        #pragma unroll
        for (int e = 0; e < E; e++) {
            if (e == e0) continue;
            if (e1 < 0 || lg[e] > lg[e1]) e1 = e;
        }
        float d = expf(lg[e1] - lg[e0]);
        float w0 = 1.f / (1.f + d);
        float w1v = d / (1.f + d);
        int p0 = atomicAdd(&g_cnt[e0], 1);
        g_tok[e0][p0] = t; g_wt[e0][p0] = w0;
        int p1 = atomicAdd(&g_cnt[e1], 1);
        g_tok[e1][p1] = t; g_wt[e1][p1] = w1v;
    }
}

__global__ void prefix_kernel() {
    if (threadIdx.x == 0 && blockIdx.x == 0) {
        int acc = 0;
        #pragma unroll
        for (int e = 0; e < E; e++) { g_off[e] = acc; acc += g_cnt[e]; }
    }
}

// ---------------- shared mainloop machinery ----------------
struct Frags {
    float acc[4][4][4];
};

__device__ __forceinline__ void mma_stage(uint32_t sb, int stage, int warp_m, int warp_n,
                                          int lane, float (*acc)[4][4]) {
    int lr = lane & 15;
    uint32_t lc16 = (lane >> 4) * 16;   // byte offset for 8-col half
    uint32_t ah_b = sb + OFF_T(stage, 0), al_b = sb + OFF_T(stage, 1);
    uint32_t bh_b = sb + OFF_T(stage, 2), bl_b = sb + OFF_T(stage, 3);
    #pragma unroll
    for (int kk = 0; kk < 2; kk++) {
        uint32_t colb = kk * 32 + lc16;
        uint32_t Ah[4][4], Al[4][4], Bh[4][2], Bl[4][2];
        #pragma unroll
        for (int im = 0; im < 4; im++) {
            uint32_t aoff = (uint32_t)(warp_m * 64 + im * 16 + lr) * RSB + colb;
            ldsm4(Ah[im], ah_b + aoff);
            ldsm4(Al[im], al_b + aoff);
        }
        #pragma unroll
        for (int in2 = 0; in2 < 2; in2++) {
            uint32_t boff = (uint32_t)(warp_n * 32 + in2 * 16 + lr) * RSB + colb;
            uint32_t t[4];
            ldsm4(t, bh_b + boff);
            Bh[2 * in2][0] = t[0]; Bh[2 * in2][1] = t[2];
            Bh[2 * in2 + 1][0] = t[1]; Bh[2 * in2 + 1][1] = t[3];
            ldsm4(t, bl_b + boff);
            Bl[2 * in2][0] = t[0]; Bl[2 * in2][1] = t[2];
            Bl[2 * in2 + 1][0] = t[1]; Bl[2 * in2 + 1][1] = t[3];
        }
        #pragma unroll
        for (int im = 0; im < 4; im++)
            #pragma unroll
            for (int in = 0; in < 4; in++) {
                mma16816(acc[im][in], Ah[im], Bh[in]);
                mma16816(acc[im][in], Ah[im], Bl[in]);
                mma16816(acc[im][in], Al[im], Bh[in]);
            }
    }
}

// ---------------- kernel 2: grouped GEMM1 (cp.async + mma.sync) + silu ----------------
__global__ __launch_bounds__(256, 1) void gemm1_tc(const float* __restrict__ xdummy) {
    extern __shared__ char smem[];
    int e = blockIdx.z;
    int cnt = g_cnt[e];
    int m0 = blockIdx.y * BM;
    if (m0 >= cnt) return;
    int n0 = blockIdx.x * BN;
    int base = g_off[e];
    int tid = threadIdx.x, wid = tid >> 5, lane = tid & 31;

    int* stok = (int*)(smem + SM_TOK);
    if (tid < BM) {
        int m = m0 + tid;
        stok[tid] = g_tok[e][m < cnt ? m : cnt - 1];
    }
    __syncthreads();
    uint32_t sb = smem_u32(smem);

    // staging: thread covers row = tid/2, half = tid&1 -> 16 bf16 (32B) per tile
    int row = tid >> 1, half = tid & 1;
    const __nv_bfloat16* ah = g_xh + (size_t)stok[row] * H + half * 16;
    const __nv_bfloat16* al = g_xl + (size_t)stok[row] * H + half * 16;
    const __nv_bfloat16* bh = g_w1h + (size_t)e * II * H + (size_t)(n0 + row) * H + half * 16;
    const __nv_bfloat16* bl = g_w1l + (size_t)e * II * H + (size_t)(n0 + row) * H + half * 16;
    uint32_t soff = (uint32_t)row * RSB + half * 32;

    int warp_m = wid >> 2, warp_n = wid & 3;

    float acc[4][4][4];
    #pragma unroll
    for (int i = 0; i < 4; i++)
        #pragma unroll
        for (int j = 0; j < 4; j++)
            #pragma unroll
            for (int q = 0; q < 4; q++) acc[i][j][q] = 0.f;

    const int NK = H / KC;   // 32

    // prologue: stages 0..STAGES-2
    #pragma unroll
    for (int s = 0; s < STAGES - 1; s++) {
        int ko = s * KC;
        cp16(sb + OFF_T(s, 0) + soff,      ah + ko);
        cp16(sb + OFF_T(s, 0) + soff + 16, ah + ko + 8);
        cp16(sb + OFF_T(s, 1) + soff,      al + ko);
        cp16(sb + OFF_T(s, 1) + soff + 16, al + ko + 8);
        cp16(sb + OFF_T(s, 2) + soff,      bh + ko);
        cp16(sb + OFF_T(s, 2) + soff + 16, bh + ko + 8);
        cp16(sb + OFF_T(s, 3) + soff,      bl + ko);
        cp16(sb + OFF_T(s, 3) + soff + 16, bl + ko + 8);
        cp_commit();
    }

    for (int kc = 0; kc < NK; kc++) {
        cp_wait<STAGES - 2>();
        __syncthreads();
        int kn = kc + STAGES - 1;
        if (kn < NK) {
            int s = kn % STAGES;
            int ko = kn * KC;
            cp16(sb + OFF_T(s, 0) + soff,      ah + ko);
            cp16(sb + OFF_T(s, 0) + soff + 16, ah + ko + 8);
            cp16(sb + OFF_T(s, 1) + soff,      al + ko);
            cp16(sb + OFF_T(s, 1) + soff + 16, al + ko + 8);
            cp16(sb + OFF_T(s, 2) + soff,      bh + ko);
            cp16(sb + OFF_T(s, 2) + soff + 16, bh + ko + 8);
            cp16(sb + OFF_T(s, 3) + soff,      bl + ko);
            cp16(sb + OFF_T(s, 3) + soff + 16, bl + ko + 8);
        }
        cp_commit();
        mma_stage(sb, kc % STAGES, warp_m, warp_n, lane, acc);
    }

    // epilogue: silu + split -> g_hid hi/lo
    int quad = lane >> 2, tq = lane & 3;
    #pragma unroll
    for (int im = 0; im < 4; im++) {
        int mA = m0 + warp_m * 64 + im * 16 + quad;
        int mB = mA + 8;
        bool aA = (mA < cnt), aB = (mB < cnt);
        size_t roA = aA ? (size_t)(base + mA) * II : 0;
        size_t roB = aB ? (size_t)(base + mB) * II : 0;
        #pragma unroll
        for (int in = 0; in < 4; in++) {
            int col = n0 + warp_n * 32 + in * 8 + tq * 2;
            if (aA) {
                float v0 = acc[im][in][0], v1 = acc[im][in][1];
                v0 = v0 / (1.f + __expf(-v0));
                v1 = v1 / (1.f + __expf(-v1));
                uint32_t hi, lo;
                split2(v0, v1, hi, lo);
                *(uint32_t*)(g_hid_hi + roA + col) = hi;
                *(uint32_t*)(g_hid_lo + roA + col) = lo;
            }
            if (aB) {
                float v0 = acc[im][in][2], v1 = acc[im][in][3];
                v0 = v0 / (1.f + __expf(-v0));
                v1 = v1 / (1.f + __expf(-v1));
                uint32_t hi, lo;
                split2(v0, v1, hi, lo);
                *(uint32_t*)(g_hid_hi + roB + col) = hi;
                *(uint32_t*)(g_hid_lo + roB + col) = lo;
            }
        }
    }
}

// ---------------- kernel 3: grouped GEMM2 (cp.async + mma.sync) + scatter-add ----------------
__global__ __launch_bounds__(256, 1) void gemm2_tc(float* __restrict__ out) {
    extern __shared__ char smem[];
    int e = blockIdx.z;
    int cnt = g_cnt[e];
    int m0 = blockIdx.y * BM;
    if (m0 >= cnt) return;
    int n0 = blockIdx.x * BN;
    int base = g_off[e];
    int tid = threadIdx.x, wid = tid >> 5, lane = tid & 31;
    uint32_t sb = smem_u32(smem);

    int row = tid >> 1, half = tid & 1;
    int am = m0 + row; if (am >= cnt) am = cnt - 1;
    const __nv_bfloat16* ah = g_hid_hi + (size_t)(base + am) * II + half * 16;
    const __nv_bfloat16* al = g_hid_lo + (size_t)(base + am) * II + half * 16;
    const __nv_bfloat16* bh = g_w2h + (size_t)e * H * II + (size_t)(n0 + row) * II + half * 16;
    const __nv_bfloat16* bl = g_w2l + (size_t)e * H * II + (size_t)(n0 + row) * II + half * 16;
    uint32_t soff = (uint32_t)row * RSB + half * 32;

    int warp_m = wid >> 2, warp_n = wid & 3;

    float acc[4][4][4];
    #pragma unroll
    for (int i = 0; i < 4; i++)
        #pragma unroll
        for (int j = 0; j < 4; j++)
            #pragma unroll
            for (int q = 0; q < 4; q++) acc[i][j][q] = 0.f;

    const int NK = II / KC;  // 128

    #pragma unroll
    for (int s = 0; s < STAGES - 1; s++) {
        int ko = s * KC;
        cp16(sb + OFF_T(s, 0) + soff,      ah + ko);
        cp16(sb + OFF_T(s, 0) + soff + 16, ah + ko + 8);
        cp16(sb + OFF_T(s, 1) + soff,      al + ko);
        cp16(sb + OFF_T(s, 1) + soff + 16, al + ko + 8);
        cp16(sb + OFF_T(s, 2) + soff,      bh + ko);
        cp16(sb + OFF_T(s, 2) + soff + 16, bh + ko + 8);
        cp16(sb + OFF_T(s, 3) + soff,      bl + ko);
        cp16(sb + OFF_T(s, 3) + soff + 16, bl + ko + 8);
        cp_commit();
    }

    for (int kc = 0; kc < NK; kc++) {
        cp_wait<STAGES - 2>();
        __syncthreads();
        int kn = kc + STAGES - 1;
        if (kn < NK) {
            int s = kn % STAGES;
            int ko = kn * KC;
            cp16(sb + OFF_T(s, 0) + soff,      ah + ko);
            cp16(sb + OFF_T(s, 0) + soff + 16, ah + ko + 8);
            cp16(sb + OFF_T(s, 1) + soff,      al + ko);
            cp16(sb + OFF_T(s, 1) + soff + 16, al + ko + 8);
            cp16(sb + OFF_T(s, 2) + soff,      bh + ko);
            cp16(sb + OFF_T(s, 2) + soff + 16, bh + ko + 8);
            cp16(sb + OFF_T(s, 3) + soff,      bl + ko);
            cp16(sb + OFF_T(s, 3) + soff + 16, bl + ko + 8);
        }
        cp_commit();
        mma_stage(sb, kc % STAGES, warp_m, warp_n, lane, acc);
    }

    // epilogue: weighted scatter-add
    int quad = lane >> 2, tq = lane & 3;
    #pragma unroll
    for (int im = 0; im < 4; im++) {
        int mA = m0 + warp_m * 64 + im * 16 + quad;
        int mB = mA + 8;
        bool aA = (mA < cnt), aB = (mB < cnt);
        int tokA = aA ? g_tok[e][mA] : 0;  float wtA = aA ? g_wt[e][mA] : 0.f;
        int tokB = aB ? g_tok[e][mB] : 0;  float wtB = aB ? g_wt[e][mB] : 0.f;
        float* oA = out + (size_t)tokA * H;
        float* oB = out + (size_t)tokB * H;
        #pragma unroll
        for (int in = 0; in < 4; in++) {
            int col = n0 + warp_n * 32 + in * 8 + tq * 2;
            if (aA) {
                atomicAdd(oA + col,     wtA * acc[im][in][0]);
                atomicAdd(oA + col + 1, wtA * acc[im][in][1]);
            }
            if (aB) {
                atomicAdd(oB + col,     wtB * acc[im][in][2]);
                atomicAdd(oB + col + 1, wtB * acc[im][in][3]);
            }
        }
    }
}

// ---------------- launch ----------------
extern "C" void kernel_launch(void* const* d_in, const int* in_sizes, int n_in,
                              void* d_out, int out_size) {
    const float* x  = (const float*)d_in[0];   // [1,2048,1024]
    const float* gw = (const float*)d_in[1];   // [8,1024]
    const float* w1 = (const float*)d_in[2];   // [8,4096,1024]
    const float* w2 = (const float*)d_in[3];   // [8,1024,4096]
    float* out = (float*)d_out;                // [1,2048,1024]

    cudaFuncSetAttribute(gemm1_tc, cudaFuncAttributeMaxDynamicSharedMemorySize, SMEM_TOTAL);
    cudaFuncSetAttribute(gemm2_tc, cudaFuncAttributeMaxDynamicSharedMemorySize, SMEM_TOTAL);

    __nv_bfloat16 *xh, *xl, *w1h, *w1l, *w2h, *w2l;
    cudaGetSymbolAddress((void**)&xh,  g_xh);
    cudaGetSymbolAddress((void**)&xl,  g_xl);
    cudaGetSymbolAddress((void**)&w1h, g_w1h);
    cudaGetSymbolAddress((void**)&w1l, g_w1l);
    cudaGetSymbolAddress((void**)&w2h, g_w2h);
    cudaGetSymbolAddress((void**)&w2l, g_w2l);

    zero_kernel<<<(T * H + 255) / 256, 256>>>(out);
    gate_kernel<<<T, 256>>>(x, gw);
    prefix_kernel<<<1, 32>>>();
    split_kernel<<<(T * H / 4 + 255) / 256, 256>>>(x, xh, xl, T * H / 4);
    split_kernel<<<(E * II * H / 4 + 255) / 256, 256>>>(w1, w1h, w1l, E * II * H / 4);
    split_kernel<<<(E * H * II / 4 + 255) / 256, 256>>>(w2, w2h, w2l, E * H * II / 4);
    gemm1_tc<<<dim3(II / BN, T / BM, E), 256, SMEM_TOTAL>>>(x);
    gemm2_tc<<<dim3(H / BN, T / BM, E), 256, SMEM_TOTAL>>>(out);
}